// round 17
// baseline (speedup 1.0000x reference)
#include <cuda_runtime.h>
#include <cuda_fp16.h>
#include <cstdint>

namespace {

constexpr int B   = 1024;
constexpr int NB  = 2;               // batches per CTA
constexpr int NG  = B / NB;          // grid = 512
constexpr int NP  = 22;
constexpr int DD  = 3;
constexpr int H   = 64;
constexpr int L   = 5;
constexpr int EPB = NP * (NP - 1);   // 462 edges
constexpr int HSF = 68;              // fp32 h/P/Q/agg stride (floats)
constexpr int MSH = 68;              // fp16 m stride (halves): 136B rows, 8B-aligned
constexpr int NT  = 512;             // 16 warps; 1 CTA/SM; 128 regs/thread

// misc (fp32) offsets
constexpr int M_WE1R = 0;    // We1 rows 128,129 (128 floats)
constexpr int M_BE1  = 128;
constexpr int M_BE2  = 192;
constexpr int M_BC1  = 256;
constexpr int M_WATT = 320;
constexpr int M_WC2  = 384;
constexpr int M_BN1  = 448;
constexpr int M_BN2  = 512;
constexpr int M_BATT = 576;
constexpr int M_SZ   = 640;

struct __align__(16) Smem {
  float  Wm[4096];            //  16,384 B  overlay: We1lo/We1hi/We2/Wc1/Wn1lo/Wn1hi/Wn2
  float  misc[M_SZ];          //   2,560 B  (shared across both batches)
  float  h[NB][NP * HSF];     //  11,968 B
  float  P[NB][NP * HSF];     //  11,968 B
  float  Q[NB][NP * HSF];     //  11,968 B
  float  agg[NB][NP * HSF];   //  11,968 B
  float  ea[NB][EPB];         //   3,696 B
  float  trans[NB][EPB * DD]; //  11,088 B
  float  coord[NB][NP * DD];  //     528 B
  __half m[NB][EPB * MSH];    // 125,664 B  m1 then GATED m2; reused as fp32 node-hidden
};                            // 207,792 B -> 1 CTA/SM, 16 warps

// ---------------- packed f32x2 helpers ----------------
__device__ __forceinline__ unsigned long long splat2(float v) {
  unsigned long long r; unsigned int u = __float_as_uint(v);
  asm("mov.b64 %0, {%1, %1};" : "=l"(r) : "r"(u)); return r;
}
__device__ __forceinline__ unsigned long long pack2(float a, float b) {
  unsigned long long r;
  asm("mov.b64 %0, {%1, %2};" : "=l"(r) : "r"(__float_as_uint(a)), "r"(__float_as_uint(b)));
  return r;
}
__device__ __forceinline__ unsigned long long ffma2(unsigned long long a,
                                                    unsigned long long b,
                                                    unsigned long long c) {
  unsigned long long d;
  asm("fma.rn.f32x2 %0, %1, %2, %3;" : "=l"(d) : "l"(a), "l"(b), "l"(c));
  return d;
}
__device__ __forceinline__ void unpack2(unsigned long long v, float& lo, float& hi) {
  unsigned int a, b;
  asm("mov.b64 {%0, %1}, %2;" : "=r"(a), "=r"(b) : "l"(v));
  lo = __uint_as_float(a); hi = __uint_as_float(b);
}
__device__ __forceinline__ float silu_f(float x) {
  return __fdividef(x, 1.0f + __expf(-x));
}
__device__ __forceinline__ uint32_t h2pack(float a, float b) {
  __half2 h = __floats2half2_rn(a, b);
  return *reinterpret_cast<uint32_t*>(&h);
}
__device__ __forceinline__ float2 h2unpack(uint32_t u) {
  __half2 h = *reinterpret_cast<__half2*>(&u);
  return __half22float2(h);
}

// half-width (32 outputs) k-step, TWO edges (batch0/batch1): LDS.128 feeds 4 FFMA2
__device__ __forceinline__ void ghalf2(unsigned long long a0[16],
                                       unsigned long long a1[16],
                                       const ulonglong2* __restrict__ wrow,
                                       unsigned long long in0,
                                       unsigned long long in1) {
#pragma unroll
  for (int i = 0; i < 8; i++) {
    ulonglong2 u = wrow[i];                 // broadcast LDS.128
    a0[2 * i]     = ffma2(in0, u.x, a0[2 * i]);
    a1[2 * i]     = ffma2(in1, u.x, a1[2 * i]);
    a0[2 * i + 1] = ffma2(in0, u.y, a0[2 * i + 1]);
    a1[2 * i + 1] = ffma2(in1, u.y, a1[2 * i + 1]);
  }
}

// one GEMV half-pass (32 outputs) over 64 fp16 inputs for two edges, LDS.64 inputs
__device__ __forceinline__ void gemv_half(unsigned long long a0[16],
                                          unsigned long long a1[16],
                                          const __half* __restrict__ me0,
                                          const __half* __restrict__ me1,
                                          const ulonglong2* __restrict__ Wh) {
#pragma unroll 2
  for (int k0 = 0; k0 < H; k0 += 4) {
    const uint2 u0 = *reinterpret_cast<const uint2*>(me0 + k0);   // LDS.64
    const uint2 u1 = *reinterpret_cast<const uint2*>(me1 + k0);
    const float2 v0a = h2unpack(u0.x), v0b = h2unpack(u0.y);
    const float2 v1a = h2unpack(u1.x), v1b = h2unpack(u1.y);
    ghalf2(a0, a1, Wh + (k0 + 0) * 16, splat2(v0a.x), splat2(v1a.x));
    ghalf2(a0, a1, Wh + (k0 + 1) * 16, splat2(v0a.y), splat2(v1a.y));
    ghalf2(a0, a1, Wh + (k0 + 2) * 16, splat2(v0b.x), splat2(v1b.x));
    ghalf2(a0, a1, Wh + (k0 + 3) * 16, splat2(v0b.y), splat2(v1b.y));
  }
}

__device__ __forceinline__ void cp_f4(float* dst, const float* __restrict__ src,
                                      int nfloats, int tid) {
  float4* d = reinterpret_cast<float4*>(dst);
  const float4* s = reinterpret_cast<const float4*>(src);
  for (int i = tid; i < (nfloats >> 2); i += NT) d[i] = s[i];
}

__global__ void __launch_bounds__(NT, 1)        // 512 thr -> 128 regs, 1 CTA/SM
egnn_kernel(const float* __restrict__ t, const float* __restrict__ x,
            const float* __restrict__ h_init,
            const float* __restrict__ Wemb, const float* __restrict__ bemb,
            const float* __restrict__ We1,  const float* __restrict__ be1,
            const float* __restrict__ We2,  const float* __restrict__ be2,
            const float* __restrict__ Watt, const float* __restrict__ batt,
            const float* __restrict__ Wn1,  const float* __restrict__ bn1,
            const float* __restrict__ Wn2,  const float* __restrict__ bn2,
            const float* __restrict__ Wc1,  const float* __restrict__ bc1,
            const float* __restrict__ Wc2,
            float* __restrict__ out)
{
  extern __shared__ char smem_raw[];
  Smem& s = *reinterpret_cast<Smem*>(smem_raw);
  const int tid  = threadIdx.x;
  const int w    = tid >> 5;
  const int lane = tid & 31;
  const int bg[NB] = {(int)blockIdx.x, (int)blockIdx.x + NG};

  // ---------- node embedding (both batches) ----------
  const float tb0 = t[bg[0]], tb1 = t[bg[1]];
  for (int task = tid; task < NB * NP * H; task += NT) {
    const int bi = task / (NP * H);
    const int rest = task % (NP * H);
    const int i = rest / H, o = rest % H;
    float acc = bemb[o] + (bi ? tb1 : tb0) * Wemb[NP * H + o];
#pragma unroll
    for (int j = 0; j < NP; j++) acc += h_init[i * NP + j] * Wemb[j * H + o];
    s.h[bi][i * HSF + o] = acc;
  }
  for (int task = tid; task < NB * NP * DD; task += NT) {
    const int bi = task / (NP * DD);
    const int r  = task % (NP * DD);
    s.coord[bi][r] = x[bg[bi] * (NP * DD) + r];
  }
  __syncthreads();

  for (int task = tid; task < NB * EPB; task += NT) {
    const int bi = task / EPB;
    const int e  = task % EPB;
    const int r = e / (NP - 1), jj = e % (NP - 1);
    const int c = jj + (jj >= r ? 1 : 0);
    const float dx = s.coord[bi][r * 3 + 0] - s.coord[bi][c * 3 + 0];
    const float dy = s.coord[bi][r * 3 + 1] - s.coord[bi][c * 3 + 1];
    const float dz = s.coord[bi][r * 3 + 2] - s.coord[bi][c * 3 + 2];
    s.ea[bi][e] = dx * dx + dy * dy + dz * dz;
  }

  for (int l = 0; l < L; l++) {
    // ---------- misc + Wm <- We1 rows 0:64 ----------
    __syncthreads();
    cp_f4(s.misc + M_WE1R, We1 + l * 130 * H + 128 * H, 2 * H, tid);
    cp_f4(s.misc + M_BE1,  be1 + l * H, H, tid);
    cp_f4(s.misc + M_BE2,  be2 + l * H, H, tid);
    cp_f4(s.misc + M_BC1,  bc1 + l * H, H, tid);
    cp_f4(s.misc + M_WATT, Watt + l * H, H, tid);
    cp_f4(s.misc + M_WC2,  Wc2 + l * H, H, tid);
    cp_f4(s.misc + M_BN1,  bn1 + l * H, H, tid);
    cp_f4(s.misc + M_BN2,  bn2 + l * H, H, tid);
    if (tid == 0) s.misc[M_BATT] = batt[l];
    cp_f4(s.Wm, We1 + l * 130 * H, H * H, tid);
    __syncthreads();

    // ---------- P pass: P[bi][n] = h[bi][n] @ We1[0:64] (44 tasks / 16 warps) ----------
    {
      const unsigned long long* Wu = reinterpret_cast<const unsigned long long*>(s.Wm);
#pragma unroll 1
      for (int tau = w; tau < NB * NP; tau += NT / 32) {
        const int bi = tau >= NP ? 1 : 0;
        const int n  = bi ? tau - NP : tau;
        const float* hn = s.h[bi] + n * HSF;
        unsigned long long acc = 0ull;
#pragma unroll 4
        for (int k = 0; k < H; k++) acc = ffma2(splat2(hn[k]), Wu[k * 32 + lane], acc);
        reinterpret_cast<unsigned long long*>(s.P[bi] + n * HSF)[lane] = acc;
      }
    }
    __syncthreads();
    cp_f4(s.Wm, We1 + l * 130 * H + H * H, H * H, tid);   // rows 64:128
    __syncthreads();

    // ---------- Q pass ----------
    {
      const unsigned long long* Wu = reinterpret_cast<const unsigned long long*>(s.Wm);
#pragma unroll 1
      for (int tau = w; tau < NB * NP; tau += NT / 32) {
        const int bi = tau >= NP ? 1 : 0;
        const int n  = bi ? tau - NP : tau;
        const float* hn = s.h[bi] + n * HSF;
        unsigned long long acc = 0ull;
#pragma unroll 4
        for (int k = 0; k < H; k++) acc = ffma2(splat2(hn[k]), Wu[k * 32 + lane], acc);
        reinterpret_cast<unsigned long long*>(s.Q[bi] + n * HSF)[lane] = acc;
      }
    }
    __syncthreads();
    cp_f4(s.Wm, We2 + l * H * H, H * H, tid);
    __syncthreads();

    // ---------- edge pass A: m1 + GEMV2 + gate (tid < 462; edge e for BOTH batches) ----------
    if (tid < EPB) {
      const int e = tid;
      const int r = e / (NP - 1), jj = e % (NP - 1);
      const int c = jj + (jj >= r ? 1 : 0);
      float rad0, rad1;
      {
        const float dx0 = s.coord[0][r * 3 + 0] - s.coord[0][c * 3 + 0];
        const float dy0 = s.coord[0][r * 3 + 1] - s.coord[0][c * 3 + 1];
        const float dz0 = s.coord[0][r * 3 + 2] - s.coord[0][c * 3 + 2];
        const float dx1 = s.coord[1][r * 3 + 0] - s.coord[1][c * 3 + 0];
        const float dy1 = s.coord[1][r * 3 + 1] - s.coord[1][c * 3 + 1];
        const float dz1 = s.coord[1][r * 3 + 2] - s.coord[1][c * 3 + 2];
        rad0 = dx0 * dx0 + dy0 * dy0 + dz0 * dz0;
        rad1 = dx1 * dx1 + dy1 * dy1 + dz1 * dz1;
      }
      const float ea0 = s.ea[0][e], ea1 = s.ea[1][e];
      __half* me0 = s.m[0] + e * MSH;
      __half* me1 = s.m[1] + e * MSH;

      // m1 = silu(P_r + Q_c + rad*We1r128 + ea*We1r129 + be1) (fp32 in, STS.64 out)
      {
        const float* Pr0 = s.P[0] + r * HSF;
        const float* Qc0 = s.Q[0] + c * HSF;
        const float* Pr1 = s.P[1] + r * HSF;
        const float* Qc1 = s.Q[1] + c * HSF;
        const float* wr = s.misc + M_WE1R;
        const float* we = s.misc + M_WE1R + H;
        const float* bb = s.misc + M_BE1;
#pragma unroll
        for (int o = 0; o < H; o += 4) {
          const float4 pA = *reinterpret_cast<const float4*>(Pr0 + o);
          const float4 qA = *reinterpret_cast<const float4*>(Qc0 + o);
          const float4 pB = *reinterpret_cast<const float4*>(Pr1 + o);
          const float4 qB = *reinterpret_cast<const float4*>(Qc1 + o);
          const float4 wv = *reinterpret_cast<const float4*>(wr + o);
          const float4 ev = *reinterpret_cast<const float4*>(we + o);
          const float4 bv = *reinterpret_cast<const float4*>(bb + o);
          uint2 st;
          st.x = h2pack(silu_f(pA.x + qA.x + rad0 * wv.x + ea0 * ev.x + bv.x),
                        silu_f(pA.y + qA.y + rad0 * wv.y + ea0 * ev.y + bv.y));
          st.y = h2pack(silu_f(pA.z + qA.z + rad0 * wv.z + ea0 * ev.z + bv.z),
                        silu_f(pA.w + qA.w + rad0 * wv.w + ea0 * ev.w + bv.w));
          *reinterpret_cast<uint2*>(me0 + o) = st;
          st.x = h2pack(silu_f(pB.x + qB.x + rad1 * wv.x + ea1 * ev.x + bv.x),
                        silu_f(pB.y + qB.y + rad1 * wv.y + ea1 * ev.y + bv.y));
          st.y = h2pack(silu_f(pB.z + qB.z + rad1 * wv.z + ea1 * ev.z + bv.z),
                        silu_f(pB.w + qB.w + rad1 * wv.w + ea1 * ev.w + bv.w));
          *reinterpret_cast<uint2*>(me1 + o) = st;
        }
      }

      // GEMV2 half-width x2, m2 half-0 held packed fp16
      uint32_t h0e0[16], h0e1[16];
      float att0 = s.misc[M_BATT], att1 = att0;
      unsigned long long a0[16], a1[16];
      const unsigned long long* be2p =
          reinterpret_cast<const unsigned long long*>(s.misc + M_BE2);
      const ulonglong2* W2 = reinterpret_cast<const ulonglong2*>(s.Wm);
#pragma unroll
      for (int i = 0; i < 16; i++) { a0[i] = be2p[i]; a1[i] = be2p[i]; }
      gemv_half(a0, a1, me0, me1, W2);
#pragma unroll
      for (int i = 0; i < 16; i++) {
        float p, q;
        unpack2(a0[i], p, q);
        p = silu_f(p); q = silu_f(q);
        att0 += p * s.misc[M_WATT + 2 * i] + q * s.misc[M_WATT + 2 * i + 1];
        h0e0[i] = h2pack(p, q);
        unpack2(a1[i], p, q);
        p = silu_f(p); q = silu_f(q);
        att1 += p * s.misc[M_WATT + 2 * i] + q * s.misc[M_WATT + 2 * i + 1];
        h0e1[i] = h2pack(p, q);
      }
#pragma unroll
      for (int i = 0; i < 16; i++) { a0[i] = be2p[16 + i]; a1[i] = be2p[16 + i]; }
      gemv_half(a0, a1, me0, me1, W2 + 8);
#pragma unroll
      for (int i = 0; i < 16; i++) {
        float p, q;
        unpack2(a0[i], p, q);
        p = silu_f(p); q = silu_f(q);
        att0 += p * s.misc[M_WATT + 32 + 2 * i] + q * s.misc[M_WATT + 32 + 2 * i + 1];
        a0[i] = pack2(p, q);
        unpack2(a1[i], p, q);
        p = silu_f(p); q = silu_f(q);
        att1 += p * s.misc[M_WATT + 32 + 2 * i] + q * s.misc[M_WATT + 32 + 2 * i + 1];
        a1[i] = pack2(p, q);
      }
      const float sg0 = __fdividef(1.0f, 1.0f + __expf(-att0));
      const float sg1 = __fdividef(1.0f, 1.0f + __expf(-att1));
#pragma unroll
      for (int i = 0; i < 8; i++) {
        float2 fa = h2unpack(h0e0[2 * i]);
        float2 fb = h2unpack(h0e0[2 * i + 1]);
        uint2 st;
        st.x = h2pack(fa.x * sg0, fa.y * sg0);
        st.y = h2pack(fb.x * sg0, fb.y * sg0);
        *reinterpret_cast<uint2*>(me0 + 4 * i) = st;
        fa = h2unpack(h0e1[2 * i]);
        fb = h2unpack(h0e1[2 * i + 1]);
        st.x = h2pack(fa.x * sg1, fa.y * sg1);
        st.y = h2pack(fb.x * sg1, fb.y * sg1);
        *reinterpret_cast<uint2*>(me1 + 4 * i) = st;
      }
#pragma unroll
      for (int i = 0; i < 8; i++) {
        float pa, qa, pb, qb;
        unpack2(a0[2 * i], pa, qa);
        unpack2(a0[2 * i + 1], pb, qb);
        uint2 st;
        st.x = h2pack(pa * sg0, qa * sg0);
        st.y = h2pack(pb * sg0, qb * sg0);
        *reinterpret_cast<uint2*>(me0 + 32 + 4 * i) = st;
        unpack2(a1[2 * i], pa, qa);
        unpack2(a1[2 * i + 1], pb, qb);
        st.x = h2pack(pa * sg1, qa * sg1);
        st.y = h2pack(pb * sg1, qb * sg1);
        *reinterpret_cast<uint2*>(me1 + 32 + 4 * i) = st;
      }
    }
    __syncthreads();
    cp_f4(s.Wm, Wc1 + l * H * H, H * H, tid);
    __syncthreads();

    // ---------- edge pass B: GEMVc -> phi -> trans ----------
    if (tid < EPB) {
      const int e = tid;
      const int r = e / (NP - 1), jj = e % (NP - 1);
      const int c = jj + (jj >= r ? 1 : 0);
      const __half* me0 = s.m[0] + e * MSH;
      const __half* me1 = s.m[1] + e * MSH;
      const ulonglong2* Wc = reinterpret_cast<const ulonglong2*>(s.Wm);
      const unsigned long long* bcp =
          reinterpret_cast<const unsigned long long*>(s.misc + M_BC1);
      float phi0 = 0.0f, phi1 = 0.0f;
#pragma unroll 1
      for (int half = 0; half < 2; half++) {
        unsigned long long a0[16], a1[16];
#pragma unroll
        for (int i = 0; i < 16; i++) { a0[i] = bcp[half * 16 + i]; a1[i] = bcp[half * 16 + i]; }
        gemv_half(a0, a1, me0, me1, Wc + half * 8);
#pragma unroll
        for (int i = 0; i < 16; i++) {
          float p, q;
          unpack2(a0[i], p, q);
          phi0 += silu_f(p) * s.misc[M_WC2 + half * 32 + 2 * i]
                + silu_f(q) * s.misc[M_WC2 + half * 32 + 2 * i + 1];
          unpack2(a1[i], p, q);
          phi1 += silu_f(p) * s.misc[M_WC2 + half * 32 + 2 * i]
                + silu_f(q) * s.misc[M_WC2 + half * 32 + 2 * i + 1];
        }
      }
      const float th0 = tanhf(phi0) * 3.0f;   // COORDS_RANGE
      const float th1 = tanhf(phi1) * 3.0f;
#pragma unroll
      for (int d = 0; d < 3; d++) {
        s.trans[0][e * 3 + d] = (s.coord[0][r * 3 + d] - s.coord[0][c * 3 + d]) * th0;
        s.trans[1][e * 3 + d] = (s.coord[1][r * 3 + d] - s.coord[1][c * 3 + d]) * th1;
      }
    }
    __syncthreads();

    // ---------- agg (fp16 m sum) + coord; Wm <- Wn1 rows 0:64 ----------
    cp_f4(s.Wm, Wn1 + l * 128 * H, H * H, tid);
    for (int task = tid; task < NB * NP * H; task += NT) {
      const int bi = task / (NP * H);
      const int rest = task % (NP * H);
      const int r = rest >> 6, o = rest & 63;
      const __half* mp = s.m[bi] + (r * (NP - 1)) * MSH + o;
      float a = 0.0f;
#pragma unroll
      for (int j = 0; j < NP - 1; j++) a += __half2float(mp[j * MSH]);
      s.agg[bi][r * HSF + o] = a;
    }
    for (int task = tid; task < NB * NP * DD; task += NT) {
      const int bi = task / (NP * DD);
      const int rest = task % (NP * DD);
      const int r = rest / DD, d = rest % DD;
      const float* tp = s.trans[bi] + (r * (NP - 1)) * DD + d;
      float a = 0.0f;
#pragma unroll
      for (int j = 0; j < NP - 1; j++) a += tp[j * DD];
      s.coord[bi][rest] += a;
    }
    __syncthreads();

    // ---------- node GEMV1 part 1 (h input), 44 tasks / 16 warps ----------
    unsigned long long a1v[3];
    {
      const unsigned long long* Wu = reinterpret_cast<const unsigned long long*>(s.Wm);
      const unsigned long long bn1p =
          reinterpret_cast<const unsigned long long*>(s.misc + M_BN1)[lane];
      int rnd = 0;
#pragma unroll 1
      for (int tau = w; tau < NB * NP; tau += NT / 32, rnd++) {
        const int bi = tau >= NP ? 1 : 0;
        const int n  = bi ? tau - NP : tau;
        const float* hn = s.h[bi] + n * HSF;
        unsigned long long acc = bn1p;
#pragma unroll 4
        for (int k = 0; k < H; k++) acc = ffma2(splat2(hn[k]), Wu[k * 32 + lane], acc);
        a1v[rnd] = acc;
      }
    }
    __syncthreads();
    cp_f4(s.Wm, Wn1 + l * 128 * H + H * H, H * H, tid);   // rows 64:128
    __syncthreads();

    // ---------- node GEMV1 part 2 (agg input) -> hidden (fp32 in m[bi]) ----------
    {
      const unsigned long long* Wu = reinterpret_cast<const unsigned long long*>(s.Wm);
      int rnd = 0;
#pragma unroll 1
      for (int tau = w; tau < NB * NP; tau += NT / 32, rnd++) {
        const int bi = tau >= NP ? 1 : 0;
        const int n  = bi ? tau - NP : tau;
        const float* an = s.agg[bi] + n * HSF;
        unsigned long long acc = a1v[rnd];
#pragma unroll 4
        for (int k = 0; k < H; k++) acc = ffma2(splat2(an[k]), Wu[k * 32 + lane], acc);
        float lo, hi; unpack2(acc, lo, hi);
        reinterpret_cast<unsigned long long*>(reinterpret_cast<float*>(s.m[bi]))
            [n * 32 + lane] = pack2(silu_f(lo), silu_f(hi));
      }
    }
    __syncthreads();
    cp_f4(s.Wm, Wn2 + l * H * H, H * H, tid);
    __syncthreads();

    // ---------- node GEMV2: h += hidden @ Wn2 + bn2 ----------
    {
      const unsigned long long* Wu = reinterpret_cast<const unsigned long long*>(s.Wm);
      const unsigned long long bn2p =
          reinterpret_cast<const unsigned long long*>(s.misc + M_BN2)[lane];
#pragma unroll 1
      for (int tau = w; tau < NB * NP; tau += NT / 32) {
        const int bi = tau >= NP ? 1 : 0;
        const int n  = bi ? tau - NP : tau;
        const float* hn = reinterpret_cast<const float*>(s.m[bi]) + n * H;
        unsigned long long acc = bn2p;
#pragma unroll 4
        for (int k = 0; k < H; k++) acc = ffma2(splat2(hn[k]), Wu[k * 32 + lane], acc);
        float lo, hi; unpack2(acc, lo, hi);
        s.h[bi][n * HSF + 2 * lane]     += lo;
        s.h[bi][n * HSF + 2 * lane + 1] += hi;
      }
    }
    __syncthreads();
  }

  // ---------- output: vel = (coord - x) - mean_over_particles (both batches) ----------
  if (tid < NB * DD) {
    const int bi = tid / DD, d = tid % DD;
    float mm = 0.0f;
    for (int i = 0; i < NP; i++)
      mm += s.coord[bi][i * DD + d] - x[bg[bi] * (NP * DD) + i * DD + d];
    s.ea[bi][d] = mm * (1.0f / NP);
  }
  __syncthreads();
  for (int task = tid; task < NB * NP * DD; task += NT) {
    const int bi = task / (NP * DD);
    const int rest = task % (NP * DD);
    out[bg[bi] * (NP * DD) + rest] =
        (s.coord[bi][rest] - x[bg[bi] * (NP * DD) + rest]) - s.ea[bi][rest % DD];
  }
}

}  // namespace

extern "C" void kernel_launch(void* const* d_in, const int* in_sizes, int n_in,
                              void* d_out, int out_size) {
  (void)in_sizes; (void)n_in; (void)out_size;
  const float* t      = (const float*)d_in[0];
  const float* x      = (const float*)d_in[1];
  const float* h_init = (const float*)d_in[2];
  // d_in[3]/d_in[4] rows/cols: fixed fully-connected pattern, derived analytically
  const float* Wemb = (const float*)d_in[5];
  const float* bemb = (const float*)d_in[6];
  const float* We1  = (const float*)d_in[7];
  const float* be1  = (const float*)d_in[8];
  const float* We2  = (const float*)d_in[9];
  const float* be2  = (const float*)d_in[10];
  const float* Watt = (const float*)d_in[11];
  const float* batt = (const float*)d_in[12];
  const float* Wn1  = (const float*)d_in[13];
  const float* bn1  = (const float*)d_in[14];
  const float* Wn2  = (const float*)d_in[15];
  const float* bn2  = (const float*)d_in[16];
  const float* Wc1  = (const float*)d_in[17];
  const float* bc1  = (const float*)d_in[18];
  const float* Wc2  = (const float*)d_in[19];

  cudaFuncSetAttribute(egnn_kernel, cudaFuncAttributeMaxDynamicSharedMemorySize,
                       (int)sizeof(Smem));
  egnn_kernel<<<NG, NT, sizeof(Smem)>>>(t, x, h_init, Wemb, bemb, We1, be1, We2, be2,
                                        Watt, batt, Wn1, bn1, Wn2, bn2, Wc1, bc1, Wc2,
                                        (float*)d_out);
}